// round 8
// baseline (speedup 1.0000x reference)
#include <cuda_runtime.h>
#include <math.h>
#include <stddef.h>
#include <stdint.h>

// Problem constants
namespace {
constexpr int B_ = 4, T_ = 2048, C_ = 1024, H_ = 4, D_ = 256;
constexpr int M_ = B_ * T_;   // 8192 rows (b*T + t)
constexpr int NG = 4 * C_;    // 4096 gate columns
constexpr int NCH = 4096;     // channels
constexpr int CHK = 64;       // scan chunk length
constexpr int NC = T_ / CHK;  // 32 scan chunks

// GEMM pipeline config
constexpr int BK = 16;
constexpr int SSTR = BK + 4;                    // smem row stride (floats), conflict-free
constexpr int STG_FLOATS = 2 * 128 * SSTR;      // A(128x20) + B(128x20) per stage
constexpr int NSTG = 4;
constexpr int DYN_BYTES = NSTG * STG_FLOATS * 4; // 81920 B
}

// Scratch (static device globals). Referenced ONLY from device code:
// passing them as kernel args from host binds the host shadow (R5 bug).
__device__ float g_xc[(size_t)M_ * C_];        // conv+silu output (tf32-rounded)
__device__ float g_gates[(size_t)M_ * NG];     // gate activations
__device__ float g_h[(size_t)M_ * C_];         // scan output
__device__ float g_hn[(size_t)M_ * C_];        // normalized (tf32-rounded)
__device__ float g_wx[(size_t)NG * C_];        // tf32-rounded wx_w
__device__ float g_ow[(size_t)C_ * C_];        // tf32-rounded out_w
__device__ float4 g_summ[NC * NCH];
__device__ float4 g_inc[NC * NCH];
__device__ float g_sum[B_ * H_];
__device__ float g_sqs[B_ * H_];
__device__ float g_ns[B_ * C_];
__device__ float g_nt[B_ * C_];

__device__ __forceinline__ float to_tf32(float x) {
    uint32_t u;
    asm("cvt.rna.tf32.f32 %0, %1;" : "=r"(u) : "f"(x));
    return __uint_as_float(u);
}

__device__ __forceinline__ void cp16(void* smem, const void* gmem) {
    uint32_t s = (uint32_t)__cvta_generic_to_shared(smem);
    asm volatile("cp.async.cg.shared.global [%0], [%1], 16;"
                 :: "r"(s), "l"(gmem) : "memory");
}

// ---------------------------------------------------------------------------
// tf32 pre-rounding copy into device weight buffers
// ---------------------------------------------------------------------------
template <int WHICH>
__global__ void round_copy_kernel(const float4* __restrict__ src, int n4) {
    float4* dst = (WHICH == 0) ? (float4*)g_wx : (float4*)g_ow;
    int i = blockIdx.x * blockDim.x + threadIdx.x;
    if (i < n4) {
        float4 v = src[i];
        dst[i] = make_float4(to_tf32(v.x), to_tf32(v.y), to_tf32(v.z), to_tf32(v.w));
    }
}

__global__ void zero_stats_kernel() {
    int i = threadIdx.x;
    if (i < B_ * H_) { g_sum[i] = 0.f; g_sqs[i] = 0.f; }
}

// ---------------------------------------------------------------------------
// Causal depthwise conv (k=4, left pad 3) + bias + SiLU (tf32-rounded)
// ---------------------------------------------------------------------------
__global__ void conv_silu_kernel(const float* __restrict__ x,
                                 const float* __restrict__ cw,
                                 const float* __restrict__ cb) {
    int idx = blockIdx.x * blockDim.x + threadIdx.x;
    int c = idx & (C_ - 1);
    int m = idx >> 10;
    int t = m & (T_ - 1);
    const float* xp = x + (size_t)m * C_ + c;
    float v = cw[c * 4 + 3] * xp[0];
    if (t >= 1) v += cw[c * 4 + 2] * xp[-C_];
    if (t >= 2) v += cw[c * 4 + 1] * xp[-2 * C_];
    if (t >= 3) v += cw[c * 4 + 0] * xp[-3 * C_];
    v += cb[c];
    g_xc[idx] = to_tf32(v / (1.f + __expf(-v)));
}

// ---------------------------------------------------------------------------
// TF32 tensor-core GEMM (mma.sync.m16n8k8):  C[m,n] = sum_k A[m,k]*W[n,k]
// BM=BN=128, BK=16, 256 threads (8 warps, 64x32 warp tiles).
// 4-stage cp.async pipeline in dynamic smem; ONE __syncthreads per k-tile:
//   wait_group 2 -> sync -> issue tile c+3 into stage (c+3)%4 -> compute c%4
// Stage (c+3)%4 == (c-1)%4 was last read at iter c-1; every warp passed this
// iteration's barrier, so no reader remains -> safe with a single barrier.
// EPI=0: A=g_xc, W=g_wx, Co=g_gates (+wx_b, tanh gate2, sigmoid gate3)
// EPI=1: A=g_hn, W=g_ow, Co=param  (+out_b, +residual)
// ---------------------------------------------------------------------------
template <int EPI>
__global__ void __launch_bounds__(256, 2)
gemm_tf32_kernel(const float* __restrict__ bias,
                 const float* __restrict__ resid,
                 float* __restrict__ CoParam,
                 int M, int N, int K) {
    extern __shared__ __align__(16) float sm[];

    const float* A = (EPI == 0) ? g_xc : g_hn;
    const float* W = (EPI == 0) ? g_wx : g_ow;
    float* Co = (EPI == 0) ? g_gates : CoParam;

    const int tid = threadIdx.x;
    const int bm = blockIdx.y * 128;
    const int bn = blockIdx.x * 128;
    const int lrow = tid >> 2;          // 0..63
    const int lcol = (tid & 3) << 2;    // 0,4,8,12

    const float* Ag = A + (size_t)(bm + lrow) * K + lcol;
    const float* Bg = W + (size_t)(bn + lrow) * K + lcol;

#define ISSUE_STAGE(st, kt)                                                  \
    do {                                                                     \
        float* As_ = sm + (st) * STG_FLOATS;                                 \
        float* Bs_ = As_ + 128 * SSTR;                                       \
        cp16(&As_[lrow * SSTR + lcol],        Ag + (kt));                    \
        cp16(&As_[(lrow + 64) * SSTR + lcol], Ag + (size_t)64 * K + (kt));   \
        cp16(&Bs_[lrow * SSTR + lcol],        Bg + (kt));                    \
        cp16(&Bs_[(lrow + 64) * SSTR + lcol], Bg + (size_t)64 * K + (kt));   \
        asm volatile("cp.async.commit_group;" ::: "memory");                 \
    } while (0)

    // Prologue: 3 tiles in flight
    ISSUE_STAGE(0, 0);
    ISSUE_STAGE(1, BK);
    ISSUE_STAGE(2, 2 * BK);

    const int wid = tid >> 5;
    const int lane = tid & 31;
    const int wm = (wid & 1) * 64;      // warp row offset
    const int wn = (wid >> 1) * 32;     // warp col offset
    const int qr = lane >> 2;           // 0..7
    const int qc = lane & 3;            // 0..3

    float acc[4][4][4];
#pragma unroll
    for (int i = 0; i < 4; i++)
#pragma unroll
        for (int j = 0; j < 4; j++)
#pragma unroll
            for (int k = 0; k < 4; k++) acc[i][j][k] = 0.f;

    const int nk = K / BK;
    for (int it = 0; it < nk; it++) {
        const int allow = nk - 1 - it;
        if (allow >= 2)      asm volatile("cp.async.wait_group 2;" ::: "memory");
        else if (allow == 1) asm volatile("cp.async.wait_group 1;" ::: "memory");
        else                 asm volatile("cp.async.wait_group 0;" ::: "memory");
        __syncthreads();

        if (it + 3 < nk) ISSUE_STAGE((it + 3) & (NSTG - 1), (it + 3) * BK);

        const float* As_ = sm + (it & (NSTG - 1)) * STG_FLOATS;
        const float* Bs_ = As_ + 128 * SSTR;

#pragma unroll
        for (int kk0 = 0; kk0 < BK; kk0 += 8) {
            uint32_t af[4][4], bf[4][2];
#pragma unroll
            for (int mt = 0; mt < 4; mt++) {
                int r = wm + mt * 16 + qr;
                af[mt][0] = __float_as_uint(As_[r * SSTR + kk0 + qc]);
                af[mt][1] = __float_as_uint(As_[(r + 8) * SSTR + kk0 + qc]);
                af[mt][2] = __float_as_uint(As_[r * SSTR + kk0 + qc + 4]);
                af[mt][3] = __float_as_uint(As_[(r + 8) * SSTR + kk0 + qc + 4]);
            }
#pragma unroll
            for (int nt = 0; nt < 4; nt++) {
                int r = wn + nt * 8 + qr;
                bf[nt][0] = __float_as_uint(Bs_[r * SSTR + kk0 + qc]);
                bf[nt][1] = __float_as_uint(Bs_[r * SSTR + kk0 + qc + 4]);
            }
#pragma unroll
            for (int mt = 0; mt < 4; mt++)
#pragma unroll
                for (int nt = 0; nt < 4; nt++) {
                    float* c = acc[mt][nt];
                    asm volatile(
                        "mma.sync.aligned.m16n8k8.row.col.f32.tf32.tf32.f32 "
                        "{%0,%1,%2,%3}, {%4,%5,%6,%7}, {%8,%9}, {%0,%1,%2,%3};"
                        : "+f"(c[0]), "+f"(c[1]), "+f"(c[2]), "+f"(c[3])
                        : "r"(af[mt][0]), "r"(af[mt][1]), "r"(af[mt][2]), "r"(af[mt][3]),
                          "r"(bf[nt][0]), "r"(bf[nt][1]));
                }
        }
    }
#undef ISSUE_STAGE

    // Epilogue. Within a block the gate index (col>>10) is uniform.
    const int gate = bn >> 10;
#pragma unroll
    for (int mt = 0; mt < 4; mt++) {
#pragma unroll
        for (int nt = 0; nt < 4; nt++) {
            int r0 = bm + wm + mt * 16 + qr;
            int cc = bn + wn + nt * 8 + 2 * qc;
            float2 bb = *(const float2*)(&bias[cc]);
            float v0 = acc[mt][nt][0] + bb.x;
            float v1 = acc[mt][nt][1] + bb.y;
            float v2 = acc[mt][nt][2] + bb.x;
            float v3 = acc[mt][nt][3] + bb.y;
            size_t o0 = (size_t)r0 * N + cc;
            size_t o1 = (size_t)(r0 + 8) * N + cc;
            if (EPI == 0) {
                if (gate == 2) {          // z gate: tanh
                    v0 = tanhf(v0); v1 = tanhf(v1);
                    v2 = tanhf(v2); v3 = tanhf(v3);
                } else if (gate == 3) {   // o gate: sigmoid
                    v0 = __fdividef(1.f, 1.f + __expf(-v0));
                    v1 = __fdividef(1.f, 1.f + __expf(-v1));
                    v2 = __fdividef(1.f, 1.f + __expf(-v2));
                    v3 = __fdividef(1.f, 1.f + __expf(-v3));
                }
            } else {
                float2 r0v = *(const float2*)(&resid[o0]);
                float2 r1v = *(const float2*)(&resid[o1]);
                v0 += r0v.x; v1 += r0v.y;
                v2 += r1v.x; v3 += r1v.y;
            }
            *(float2*)(&Co[o0]) = make_float2(v0, v1);
            *(float2*)(&Co[o1]) = make_float2(v2, v3);
        }
    }
}

// ---------------------------------------------------------------------------
// Chunked parallel sLSTM scan (pair trick: 1 exp per step)
// ---------------------------------------------------------------------------
__global__ void __launch_bounds__(128) scan_a_kernel() {
    int ch = blockIdx.x * 128 + threadIdx.x;
    int ck = blockIdx.y;
    int b = ch >> 10, hd = ch & 1023;
    const float* Gp = g_gates + (size_t)b * T_ * NG + (size_t)ck * CHK * NG + hd;

    float F = 0.f, G = -3e38f, Pz = 0.f, Pn = 0.f;
#pragma unroll 4
    for (int j = 0; j < CHK; j++) {
        const float* p = Gp + (size_t)j * NG;
        float ig = p[0], fg = p[C_], zg = p[2 * C_];
        float u = fg + G - ig;
        float mn = ig + fmaxf(u, 0.f);
        float e = __expf(-fabsf(u));
        float ip = (u >= 0.f) ? e : 1.f;
        float fp = (u >= 0.f) ? 1.f : e;
        Pz = fp * Pz + ip * zg;
        Pn = fp * Pn + ip;
        G = mn;
        F += fg;
    }
    g_summ[ck * NCH + ch] = make_float4(F, G, Pz, Pn);
}

__global__ void __launch_bounds__(128) scan_b_kernel() {
    int ch = blockIdx.x * 128 + threadIdx.x;
    float c = 0.f, n = 1.f, m = 0.f;
#pragma unroll
    for (int j = 0; j < NC; j++) {
        g_inc[j * NCH + ch] = make_float4(c, n, m, 0.f);
        float4 s = g_summ[j * NCH + ch];
        float u = m + s.x - s.y;
        float mo = s.y + fmaxf(u, 0.f);
        float e = __expf(-fabsf(u));
        float a1 = (u >= 0.f) ? 1.f : e;
        float a2 = (u >= 0.f) ? e : 1.f;
        c = a1 * c + a2 * s.z;
        n = a1 * n + a2 * s.w;
        m = mo;
    }
}

__global__ void __launch_bounds__(128) scan_c_kernel() {
    int ch = blockIdx.x * 128 + threadIdx.x;
    int ck = blockIdx.y;
    int b = ch >> 10, hd = ch & 1023;
    const float* Gp = g_gates + (size_t)b * T_ * NG + (size_t)ck * CHK * NG + hd;
    float* hp = g_h + (size_t)b * T_ * C_ + (size_t)ck * CHK * C_ + hd;

    float4 st = g_inc[ck * NCH + ch];
    float c = st.x, n = st.y, m = st.z;
    float s1 = 0.f, s2 = 0.f;

#pragma unroll 4
    for (int j = 0; j < CHK; j++) {
        const float* p = Gp + (size_t)j * NG;
        float ig = p[0], fg = p[C_], zg = p[2 * C_], sg = p[3 * C_];
        float u = fg + m - ig;
        float mn = ig + fmaxf(u, 0.f);
        float e = __expf(-fabsf(u));
        float ip = (u >= 0.f) ? e : 1.f;
        float fp = (u >= 0.f) ? 1.f : e;
        c = fp * c + ip * zg;
        n = fp * n + ip;
        float h = __fdividef(sg * c, n + 1e-6f);
        hp[(size_t)j * C_] = h;
        s1 += h;
        s2 += h * h;
        m = mn;
    }
#pragma unroll
    for (int o = 16; o > 0; o >>= 1) {
        s1 += __shfl_down_sync(0xffffffffu, s1, o);
        s2 += __shfl_down_sync(0xffffffffu, s2, o);
    }
    if ((threadIdx.x & 31) == 0) {
        int grp = (b << 2) + (hd >> 8);
        atomicAdd(&g_sum[grp], s1);
        atomicAdd(&g_sqs[grp], s2);
    }
}

__global__ void prep_norm_kernel(const float* __restrict__ gn_w,
                                 const float* __restrict__ gn_b) {
    int idx = blockIdx.x * blockDim.x + threadIdx.x;
    int b = idx >> 10;
    int c = idx & (C_ - 1);
    int grp = (b << 2) + (c >> 8);
    const float inv_cnt = 1.f / (float)(T_ * D_);
    float mean = g_sum[grp] * inv_cnt;
    float var = g_sqs[grp] * inv_cnt - mean * mean;
    float rstd = rsqrtf(var + 1e-5f);
    float s = rstd * gn_w[c];
    g_ns[idx] = s;
    g_nt[idx] = gn_b[c] - mean * s;
}

__global__ void normalize_kernel() {
    int idx = blockIdx.x * blockDim.x + threadIdx.x;
    int c = idx & (C_ - 1);
    int b = idx >> 21;
    int bc = (b << 10) + c;
    g_hn[idx] = to_tf32(g_h[idx] * g_ns[bc] + g_nt[bc]);
}

// ---------------------------------------------------------------------------
// Launch
// ---------------------------------------------------------------------------
extern "C" void kernel_launch(void* const* d_in, const int* in_sizes, int n_in,
                              void* d_out, int out_size) {
    const float* x      = (const float*)d_in[0];
    const float* conv_w = (const float*)d_in[1];
    const float* conv_b = (const float*)d_in[2];
    const float* wx_w   = (const float*)d_in[3];
    const float* wx_b   = (const float*)d_in[4];
    const float* gn_w   = (const float*)d_in[5];
    const float* gn_b   = (const float*)d_in[6];
    const float* out_w  = (const float*)d_in[7];
    const float* out_b  = (const float*)d_in[8];
    float* out = (float*)d_out;

    (void)in_sizes; (void)n_in; (void)out_size;

    cudaFuncSetAttribute(gemm_tf32_kernel<0>,
                         cudaFuncAttributeMaxDynamicSharedMemorySize, DYN_BYTES);
    cudaFuncSetAttribute(gemm_tf32_kernel<1>,
                         cudaFuncAttributeMaxDynamicSharedMemorySize, DYN_BYTES);

    // 0) pre-round weights to tf32
    round_copy_kernel<0><<<(NG * C_ / 4 + 255) / 256, 256>>>(
        (const float4*)wx_w, NG * C_ / 4);
    round_copy_kernel<1><<<(C_ * C_ / 4 + 255) / 256, 256>>>(
        (const float4*)out_w, C_ * C_ / 4);

    // 1) conv + silu (tf32-rounded)
    conv_silu_kernel<<<(M_ * C_) / 256, 256>>>(x, conv_w, conv_b);

    // 2) gates GEMM (+bias, tanh on z, sigmoid on o)
    {
        dim3 g(NG / 128, M_ / 128);
        gemm_tf32_kernel<0><<<g, 256, DYN_BYTES>>>(wx_b, nullptr, nullptr,
                                                   M_, NG, C_);
    }

    // 3) parallel scan (+GroupNorm stats), norm coefficients, apply norm
    zero_stats_kernel<<<1, 32>>>();
    {
        dim3 g(NCH / 128, NC);
        scan_a_kernel<<<g, 128>>>();
        scan_b_kernel<<<NCH / 128, 128>>>();
        scan_c_kernel<<<g, 128>>>();
    }
    prep_norm_kernel<<<B_ * C_ / 256, 256>>>(gn_w, gn_b);
    normalize_kernel<<<(M_ * C_) / 256, 256>>>();

    // 4) output GEMM (+bias, +residual) -> d_out
    {
        dim3 g(C_ / 128, M_ / 128);
        gemm_tf32_kernel<1><<<g, 256, DYN_BYTES>>>(out_b, x, out, M_, C_, C_);
    }
}

// round 10
// speedup vs baseline: 1.6325x; 1.6325x over previous
#include <cuda_runtime.h>
#include <cuda_fp16.h>
#include <math.h>
#include <stddef.h>
#include <stdint.h>

// Problem constants
namespace {
constexpr int B_ = 4, T_ = 2048, C_ = 1024, H_ = 4, D_ = 256;
constexpr int M_ = B_ * T_;   // 8192 rows (b*T + t)
constexpr int NG = 4 * C_;    // 4096 gate columns
constexpr int NCH = 4096;     // channels
constexpr int CHK = 64;       // scan chunk length
constexpr int NC = T_ / CHK;  // 32 scan chunks

// GEMM pipeline config (fp16 operands)
constexpr int BK = 32;                      // halfs per k-tile (64 B rows)
constexpr int SSTR = 40;                    // smem row stride in halfs (80 B)
constexpr int STG_HALFS = 2 * 128 * SSTR;   // A + B per stage
constexpr int NSTG = 4;
constexpr int DYN_BYTES = NSTG * STG_HALFS * 2;  // 81920 B
}

// Scratch (static device globals). Referenced ONLY from device code:
// passing them as kernel args from host binds the host shadow (R5 bug).
__device__ __half g_xc[(size_t)M_ * C_];     // conv+silu output (fp16)
__device__ float g_gates[(size_t)M_ * NG];   // gate activations (fp32)
__device__ float g_h[(size_t)M_ * C_];       // scan output
__device__ __half g_hn[(size_t)M_ * C_];     // normalized (fp16)
__device__ __half g_wx[(size_t)NG * C_];     // fp16 wx_w
__device__ __half g_ow[(size_t)C_ * C_];     // fp16 out_w
__device__ float4 g_summ[NC * NCH];
__device__ float4 g_inc[NC * NCH];
__device__ float g_sum[B_ * H_];
__device__ float g_sqs[B_ * H_];
__device__ float g_ns[B_ * C_];
__device__ float g_nt[B_ * C_];

__device__ __forceinline__ void cp16(void* smem, const void* gmem) {
    uint32_t s = (uint32_t)__cvta_generic_to_shared(smem);
    asm volatile("cp.async.cg.shared.global [%0], [%1], 16;"
                 :: "r"(s), "l"(gmem) : "memory");
}

__device__ __forceinline__ void ldsm_x4(uint32_t& r0, uint32_t& r1,
                                        uint32_t& r2, uint32_t& r3,
                                        const __half* p) {
    uint32_t a = (uint32_t)__cvta_generic_to_shared(p);
    asm volatile("ldmatrix.sync.aligned.m8n8.x4.shared.b16 {%0,%1,%2,%3}, [%4];"
                 : "=r"(r0), "=r"(r1), "=r"(r2), "=r"(r3) : "r"(a));
}

// ---------------------------------------------------------------------------
// fp16 conversion copy into device weight buffers
// ---------------------------------------------------------------------------
template <int WHICH>
__global__ void half_copy_kernel(const float4* __restrict__ src, int n4) {
    __half2* dst = (WHICH == 0) ? (__half2*)g_wx : (__half2*)g_ow;
    int i = blockIdx.x * blockDim.x + threadIdx.x;
    if (i < n4) {
        float4 v = src[i];
        dst[2 * i]     = __floats2half2_rn(v.x, v.y);
        dst[2 * i + 1] = __floats2half2_rn(v.z, v.w);
    }
}

__global__ void zero_stats_kernel() {
    int i = threadIdx.x;
    if (i < B_ * H_) { g_sum[i] = 0.f; g_sqs[i] = 0.f; }
}

// ---------------------------------------------------------------------------
// Causal depthwise conv (k=4, left pad 3) + bias + SiLU (fp16 output)
// ---------------------------------------------------------------------------
__global__ void conv_silu_kernel(const float* __restrict__ x,
                                 const float* __restrict__ cw,
                                 const float* __restrict__ cb) {
    int idx = blockIdx.x * blockDim.x + threadIdx.x;
    int c = idx & (C_ - 1);
    int m = idx >> 10;
    int t = m & (T_ - 1);
    const float* xp = x + (size_t)m * C_ + c;
    float v = cw[c * 4 + 3] * xp[0];
    if (t >= 1) v += cw[c * 4 + 2] * xp[-C_];
    if (t >= 2) v += cw[c * 4 + 1] * xp[-2 * C_];
    if (t >= 3) v += cw[c * 4 + 0] * xp[-3 * C_];
    v += cb[c];
    g_xc[idx] = __float2half_rn(v / (1.f + __expf(-v)));
}

// ---------------------------------------------------------------------------
// FP16 tensor-core GEMM (mma.sync.m16n8k16, f32 accum):
//   C[m,n] = sum_k A[m,k] * W[n,k]   (both K-contiguous)
// BM=BN=128, BK=32, 256 threads (8 warps, 64x32 warp tiles).
// Fragments via ldmatrix.x4; smem rows 80 B stride (conflict-free for both
// cp.async 16B stores and ldmatrix row gathers: banks (20r+4j) mod 32 distinct).
// 4-stage cp.async pipeline, one __syncthreads per k-tile.
// EPI=0: A=g_xc, W=g_wx, Co=g_gates (+wx_b, tanh gate2, sigmoid gate3)
// EPI=1: A=g_hn, W=g_ow, Co=param  (+out_b, +residual)
// ---------------------------------------------------------------------------
template <int EPI>
__global__ void __launch_bounds__(256, 2)
gemm_fp16_kernel(const float* __restrict__ bias,
                 const float* __restrict__ resid,
                 float* __restrict__ CoParam,
                 int M, int N, int K) {
    extern __shared__ __align__(16) __half sm[];

    const __half* A = (EPI == 0) ? g_xc : g_hn;
    const __half* W = (EPI == 0) ? g_wx : g_ow;
    float* Co = (EPI == 0) ? g_gates : CoParam;

    const int tid = threadIdx.x;
    const int bm = blockIdx.y * 128;
    const int bn = blockIdx.x * 128;

    const __half* Abase = A + (size_t)bm * K;
    const __half* Bbase = W + (size_t)bn * K;

    // loader: 128 rows x 64 B = 512 16B-chunks per operand; 2 per thread
#define ISSUE_STAGE(st, kt)                                                 \
    do {                                                                    \
        __half* As_ = sm + (st) * STG_HALFS;                                \
        __half* Bs_ = As_ + 128 * SSTR;                                     \
        _Pragma("unroll")                                                   \
        for (int kc = 0; kc < 2; kc++) {                                    \
            int u = tid + 256 * kc;                                         \
            int r = u >> 2, j = u & 3;                                      \
            cp16(&As_[r * SSTR + j * 8], Abase + (size_t)r * K + (kt) + j * 8); \
            cp16(&Bs_[r * SSTR + j * 8], Bbase + (size_t)r * K + (kt) + j * 8); \
        }                                                                   \
        asm volatile("cp.async.commit_group;" ::: "memory");                \
    } while (0)

    ISSUE_STAGE(0, 0);
    ISSUE_STAGE(1, BK);
    ISSUE_STAGE(2, 2 * BK);

    const int wid = tid >> 5;
    const int lane = tid & 31;
    const int wm = (wid & 1) * 64;      // warp row offset
    const int wn = (wid >> 1) * 32;     // warp col offset
    const int qr = lane >> 2;           // 0..7
    const int qc = lane & 3;            // 0..3
    // ldmatrix lane->row/k mapping (x4: m0 r0-7 k0, m1 r8-15 k0, m2 r0-7 k8, m3 r8-15 k8)
    const int grp = lane >> 3;
    const int row_off = ((grp & 1) << 3) + (lane & 7);
    const int k_off = (grp >> 1) << 3;

    float acc[4][4][4];
#pragma unroll
    for (int i = 0; i < 4; i++)
#pragma unroll
        for (int j = 0; j < 4; j++)
#pragma unroll
            for (int k = 0; k < 4; k++) acc[i][j][k] = 0.f;

    const int nk = K / BK;
    for (int it = 0; it < nk; it++) {
        const int allow = nk - 1 - it;
        if (allow >= 2)      asm volatile("cp.async.wait_group 2;" ::: "memory");
        else if (allow == 1) asm volatile("cp.async.wait_group 1;" ::: "memory");
        else                 asm volatile("cp.async.wait_group 0;" ::: "memory");
        __syncthreads();

        if (it + 3 < nk) ISSUE_STAGE((it + 3) & (NSTG - 1), (it + 3) * BK);

        const __half* As_ = sm + (it & (NSTG - 1)) * STG_HALFS;
        const __half* Bs_ = As_ + 128 * SSTR;

#pragma unroll
        for (int kk0 = 0; kk0 < BK; kk0 += 16) {
            uint32_t af[4][4], bf[4][2];
#pragma unroll
            for (int mt = 0; mt < 4; mt++) {
                ldsm_x4(af[mt][0], af[mt][1], af[mt][2], af[mt][3],
                        &As_[(wm + mt * 16 + row_off) * SSTR + kk0 + k_off]);
            }
#pragma unroll
            for (int nb = 0; nb < 2; nb++) {
                uint32_t q0, q1, q2, q3;
                ldsm_x4(q0, q1, q2, q3,
                        &Bs_[(wn + nb * 16 + row_off) * SSTR + kk0 + k_off]);
                bf[2 * nb][0] = q0; bf[2 * nb + 1][0] = q1;
                bf[2 * nb][1] = q2; bf[2 * nb + 1][1] = q3;
            }
#pragma unroll
            for (int mt = 0; mt < 4; mt++)
#pragma unroll
                for (int nt = 0; nt < 4; nt++) {
                    float* c = acc[mt][nt];
                    asm volatile(
                        "mma.sync.aligned.m16n8k16.row.col.f32.f16.f16.f32 "
                        "{%0,%1,%2,%3}, {%4,%5,%6,%7}, {%8,%9}, {%0,%1,%2,%3};"
                        : "+f"(c[0]), "+f"(c[1]), "+f"(c[2]), "+f"(c[3])
                        : "r"(af[mt][0]), "r"(af[mt][1]), "r"(af[mt][2]), "r"(af[mt][3]),
                          "r"(bf[nt][0]), "r"(bf[nt][1]));
                }
        }
    }
#undef ISSUE_STAGE

    // Epilogue. Within a block the gate index (col>>10) is uniform.
    const int gate = bn >> 10;
#pragma unroll
    for (int mt = 0; mt < 4; mt++) {
#pragma unroll
        for (int nt = 0; nt < 4; nt++) {
            int r0 = bm + wm + mt * 16 + qr;
            int cc = bn + wn + nt * 8 + 2 * qc;
            float2 bb = *(const float2*)(&bias[cc]);
            float v0 = acc[mt][nt][0] + bb.x;
            float v1 = acc[mt][nt][1] + bb.y;
            float v2 = acc[mt][nt][2] + bb.x;
            float v3 = acc[mt][nt][3] + bb.y;
            size_t o0 = (size_t)r0 * N + cc;
            size_t o1 = (size_t)(r0 + 8) * N + cc;
            if (EPI == 0) {
                if (gate == 2) {          // z gate: tanh
                    v0 = tanhf(v0); v1 = tanhf(v1);
                    v2 = tanhf(v2); v3 = tanhf(v3);
                } else if (gate == 3) {   // o gate: sigmoid
                    v0 = __fdividef(1.f, 1.f + __expf(-v0));
                    v1 = __fdividef(1.f, 1.f + __expf(-v1));
                    v2 = __fdividef(1.f, 1.f + __expf(-v2));
                    v3 = __fdividef(1.f, 1.f + __expf(-v3));
                }
            } else {
                float2 r0v = *(const float2*)(&resid[o0]);
                float2 r1v = *(const float2*)(&resid[o1]);
                v0 += r0v.x; v1 += r0v.y;
                v2 += r1v.x; v3 += r1v.y;
            }
            *(float2*)(&Co[o0]) = make_float2(v0, v1);
            *(float2*)(&Co[o1]) = make_float2(v2, v3);
        }
    }
}

// ---------------------------------------------------------------------------
// Chunked parallel sLSTM scan (pair trick: 1 exp per step)
// ---------------------------------------------------------------------------
__global__ void __launch_bounds__(128) scan_a_kernel() {
    int ch = blockIdx.x * 128 + threadIdx.x;
    int ck = blockIdx.y;
    int b = ch >> 10, hd = ch & 1023;
    const float* Gp = g_gates + (size_t)b * T_ * NG + (size_t)ck * CHK * NG + hd;

    float F = 0.f, G = -3e38f, Pz = 0.f, Pn = 0.f;
#pragma unroll 4
    for (int j = 0; j < CHK; j++) {
        const float* p = Gp + (size_t)j * NG;
        float ig = p[0], fg = p[C_], zg = p[2 * C_];
        float u = fg + G - ig;
        float mn = ig + fmaxf(u, 0.f);
        float e = __expf(-fabsf(u));
        float ip = (u >= 0.f) ? e : 1.f;
        float fp = (u >= 0.f) ? 1.f : e;
        Pz = fp * Pz + ip * zg;
        Pn = fp * Pn + ip;
        G = mn;
        F += fg;
    }
    g_summ[ck * NCH + ch] = make_float4(F, G, Pz, Pn);
}

__global__ void __launch_bounds__(128) scan_b_kernel() {
    int ch = blockIdx.x * 128 + threadIdx.x;
    float c = 0.f, n = 1.f, m = 0.f;
#pragma unroll
    for (int j = 0; j < NC; j++) {
        g_inc[j * NCH + ch] = make_float4(c, n, m, 0.f);
        float4 s = g_summ[j * NCH + ch];
        float u = m + s.x - s.y;
        float mo = s.y + fmaxf(u, 0.f);
        float e = __expf(-fabsf(u));
        float a1 = (u >= 0.f) ? 1.f : e;
        float a2 = (u >= 0.f) ? e : 1.f;
        c = a1 * c + a2 * s.z;
        n = a1 * n + a2 * s.w;
        m = mo;
    }
}

__global__ void __launch_bounds__(128) scan_c_kernel() {
    int ch = blockIdx.x * 128 + threadIdx.x;
    int ck = blockIdx.y;
    int b = ch >> 10, hd = ch & 1023;
    const float* Gp = g_gates + (size_t)b * T_ * NG + (size_t)ck * CHK * NG + hd;
    float* hp = g_h + (size_t)b * T_ * C_ + (size_t)ck * CHK * C_ + hd;

    float4 st = g_inc[ck * NCH + ch];
    float c = st.x, n = st.y, m = st.z;
    float s1 = 0.f, s2 = 0.f;

#pragma unroll 4
    for (int j = 0; j < CHK; j++) {
        const float* p = Gp + (size_t)j * NG;
        float ig = p[0], fg = p[C_], zg = p[2 * C_], sg = p[3 * C_];
        float u = fg + m - ig;
        float mn = ig + fmaxf(u, 0.f);
        float e = __expf(-fabsf(u));
        float ip = (u >= 0.f) ? e : 1.f;
        float fp = (u >= 0.f) ? 1.f : e;
        c = fp * c + ip * zg;
        n = fp * n + ip;
        float h = __fdividef(sg * c, n + 1e-6f);
        hp[(size_t)j * C_] = h;
        s1 += h;
        s2 += h * h;
        m = mn;
    }
#pragma unroll
    for (int o = 16; o > 0; o >>= 1) {
        s1 += __shfl_down_sync(0xffffffffu, s1, o);
        s2 += __shfl_down_sync(0xffffffffu, s2, o);
    }
    if ((threadIdx.x & 31) == 0) {
        int grp = (b << 2) + (hd >> 8);
        atomicAdd(&g_sum[grp], s1);
        atomicAdd(&g_sqs[grp], s2);
    }
}

__global__ void prep_norm_kernel(const float* __restrict__ gn_w,
                                 const float* __restrict__ gn_b) {
    int idx = blockIdx.x * blockDim.x + threadIdx.x;
    int b = idx >> 10;
    int c = idx & (C_ - 1);
    int grp = (b << 2) + (c >> 8);
    const float inv_cnt = 1.f / (float)(T_ * D_);
    float mean = g_sum[grp] * inv_cnt;
    float var = g_sqs[grp] * inv_cnt - mean * mean;
    float rstd = rsqrtf(var + 1e-5f);
    float s = rstd * gn_w[c];
    g_ns[idx] = s;
    g_nt[idx] = gn_b[c] - mean * s;
}

__global__ void normalize_kernel() {
    int idx = blockIdx.x * blockDim.x + threadIdx.x;
    int c = idx & (C_ - 1);
    int b = idx >> 21;
    int bc = (b << 10) + c;
    g_hn[idx] = __float2half_rn(g_h[idx] * g_ns[bc] + g_nt[bc]);
}

// ---------------------------------------------------------------------------
// Launch
// ---------------------------------------------------------------------------
extern "C" void kernel_launch(void* const* d_in, const int* in_sizes, int n_in,
                              void* d_out, int out_size) {
    const float* x      = (const float*)d_in[0];
    const float* conv_w = (const float*)d_in[1];
    const float* conv_b = (const float*)d_in[2];
    const float* wx_w   = (const float*)d_in[3];
    const float* wx_b   = (const float*)d_in[4];
    const float* gn_w   = (const float*)d_in[5];
    const float* gn_b   = (const float*)d_in[6];
    const float* out_w  = (const float*)d_in[7];
    const float* out_b  = (const float*)d_in[8];
    float* out = (float*)d_out;

    (void)in_sizes; (void)n_in; (void)out_size;

    cudaFuncSetAttribute(gemm_fp16_kernel<0>,
                         cudaFuncAttributeMaxDynamicSharedMemorySize, DYN_BYTES);
    cudaFuncSetAttribute(gemm_fp16_kernel<1>,
                         cudaFuncAttributeMaxDynamicSharedMemorySize, DYN_BYTES);

    // 0) convert weights to fp16
    half_copy_kernel<0><<<(NG * C_ / 4 + 255) / 256, 256>>>(
        (const float4*)wx_w, NG * C_ / 4);
    half_copy_kernel<1><<<(C_ * C_ / 4 + 255) / 256, 256>>>(
        (const float4*)out_w, C_ * C_ / 4);

    // 1) conv + silu (fp16 output)
    conv_silu_kernel<<<(M_ * C_) / 256, 256>>>(x, conv_w, conv_b);

    // 2) gates GEMM (+bias, tanh on z, sigmoid on o)
    {
        dim3 g(NG / 128, M_ / 128);
        gemm_fp16_kernel<0><<<g, 256, DYN_BYTES>>>(wx_b, nullptr, nullptr,
                                                   M_, NG, C_);
    }

    // 3) parallel scan (+GroupNorm stats), norm coefficients, apply norm
    zero_stats_kernel<<<1, 32>>>();
    {
        dim3 g(NCH / 128, NC);
        scan_a_kernel<<<g, 128>>>();
        scan_b_kernel<<<NCH / 128, 128>>>();
        scan_c_kernel<<<g, 128>>>();
    }
    prep_norm_kernel<<<B_ * C_ / 256, 256>>>(gn_w, gn_b);
    normalize_kernel<<<(M_ * C_) / 256, 256>>>();

    // 4) output GEMM (+bias, +residual) -> d_out
    {
        dim3 g(C_ / 128, M_ / 128);
        gemm_fp16_kernel<1><<<g, 256, DYN_BYTES>>>(out_b, x, out, M_, C_, C_);
    }
}

// round 11
// speedup vs baseline: 1.6479x; 1.0095x over previous
#include <cuda_runtime.h>
#include <cuda_fp16.h>
#include <math.h>
#include <stddef.h>
#include <stdint.h>

// Problem constants
namespace {
constexpr int B_ = 4, T_ = 2048, C_ = 1024, H_ = 4, D_ = 256;
constexpr int M_ = B_ * T_;   // 8192 rows (b*T + t)
constexpr int NG = 4 * C_;    // 4096 gate columns
constexpr int NCH = 4096;     // channels
constexpr int CHK = 64;       // scan chunk length
constexpr int NC = T_ / CHK;  // 32 scan chunks

// GEMM pipeline config (fp16 operands)
constexpr int BK = 32;                      // halfs per k-tile (64 B rows)
constexpr int SSTR = 40;                    // smem row stride in halfs (80 B)
constexpr int STG_HALFS = 2 * 128 * SSTR;   // A + B per stage
constexpr int STG_BYTES = STG_HALFS * 2;
constexpr int NSTG = 4;
constexpr int DYN_BYTES = NSTG * STG_BYTES; // 81920 B
}

// Scratch (static device globals). Referenced ONLY from device code:
// passing them as kernel args from host binds the host shadow (R5 bug).
__device__ __half g_xc[(size_t)M_ * C_];     // conv+silu output (fp16)
__device__ float g_gates[(size_t)M_ * NG];   // gate activations (fp32)
__device__ float g_h[(size_t)M_ * C_];       // scan output
__device__ __half g_hn[(size_t)M_ * C_];     // normalized (fp16)
__device__ __half g_wx[(size_t)NG * C_];     // fp16 wx_w
__device__ __half g_ow[(size_t)C_ * C_];     // fp16 out_w
__device__ float4 g_summ[NC * NCH];
__device__ float4 g_inc[NC * NCH];
__device__ float g_sum[B_ * H_];
__device__ float g_sqs[B_ * H_];
__device__ float g_ns[B_ * C_];
__device__ float g_nt[B_ * C_];

__device__ __forceinline__ void cp16s(uint32_t smem_addr, const void* gmem) {
    asm volatile("cp.async.cg.shared.global [%0], [%1], 16;"
                 :: "r"(smem_addr), "l"(gmem) : "memory");
}

__device__ __forceinline__ void ldsm_x4a(uint32_t& r0, uint32_t& r1,
                                         uint32_t& r2, uint32_t& r3,
                                         uint32_t addr) {
    asm volatile("ldmatrix.sync.aligned.m8n8.x4.shared.b16 {%0,%1,%2,%3}, [%4];"
                 : "=r"(r0), "=r"(r1), "=r"(r2), "=r"(r3) : "r"(addr));
}

// ---------------------------------------------------------------------------
// fp16 conversion copy into device weight buffers
// ---------------------------------------------------------------------------
template <int WHICH>
__global__ void half_copy_kernel(const float4* __restrict__ src, int n4) {
    __half2* dst = (WHICH == 0) ? (__half2*)g_wx : (__half2*)g_ow;
    int i = blockIdx.x * blockDim.x + threadIdx.x;
    if (i < n4) {
        float4 v = src[i];
        dst[2 * i]     = __floats2half2_rn(v.x, v.y);
        dst[2 * i + 1] = __floats2half2_rn(v.z, v.w);
    }
}

__global__ void zero_stats_kernel() {
    int i = threadIdx.x;
    if (i < B_ * H_) { g_sum[i] = 0.f; g_sqs[i] = 0.f; }
}

// ---------------------------------------------------------------------------
// Causal depthwise conv (k=4, left pad 3) + bias + SiLU (fp16 output)
// ---------------------------------------------------------------------------
__global__ void conv_silu_kernel(const float* __restrict__ x,
                                 const float* __restrict__ cw,
                                 const float* __restrict__ cb) {
    int idx = blockIdx.x * blockDim.x + threadIdx.x;
    int c = idx & (C_ - 1);
    int m = idx >> 10;
    int t = m & (T_ - 1);
    const float* xp = x + (size_t)m * C_ + c;
    float v = cw[c * 4 + 3] * xp[0];
    if (t >= 1) v += cw[c * 4 + 2] * xp[-C_];
    if (t >= 2) v += cw[c * 4 + 1] * xp[-2 * C_];
    if (t >= 3) v += cw[c * 4 + 0] * xp[-3 * C_];
    v += cb[c];
    g_xc[idx] = __float2half_rn(v / (1.f + __expf(-v)));
}

// ---------------------------------------------------------------------------
// FP16 tensor-core GEMM (mma.sync.m16n8k16, f32 accum):
//   C[m,n] = sum_k A[m,k] * W[n,k]   (both K-contiguous)
// BM=BN=128, BK=32, 256 threads (8 warps, 64x32 warp tiles).
// ALL smem addresses precomputed as uint32 (one cvta); inner loop does only
// +stage_offset adds -> ALU pipe freed for HMMA issue.
// 4-stage cp.async pipeline, one __syncthreads per k-tile.
// EPI=0: A=g_xc, W=g_wx, Co=g_gates (+wx_b, tanh gate2, sigmoid gate3)
// EPI=1: A=g_hn, W=g_ow, Co=param  (+out_b, +residual)
// ---------------------------------------------------------------------------
template <int EPI>
__global__ void __launch_bounds__(256, 2)
gemm_fp16_kernel(const float* __restrict__ bias,
                 const float* __restrict__ resid,
                 float* __restrict__ CoParam,
                 int M, int N, int K) {
    extern __shared__ __align__(16) __half sm[];

    const __half* A = (EPI == 0) ? g_xc : g_hn;
    const __half* W = (EPI == 0) ? g_wx : g_ow;
    float* Co = (EPI == 0) ? g_gates : CoParam;

    const int tid = threadIdx.x;
    const int bm = blockIdx.y * 128;
    const int bn = blockIdx.x * 128;

    const uint32_t smbase = (uint32_t)__cvta_generic_to_shared(sm);

    // ---- loader address precompute (2 x 16B chunks per operand per thread)
    uint32_t cp_a[2], cp_b[2];
    const __half* gm_a[2];
    const __half* gm_b[2];
    {
        const __half* Abase = A + (size_t)bm * K;
        const __half* Bbase = W + (size_t)bn * K;
#pragma unroll
        for (int kc = 0; kc < 2; kc++) {
            int u = tid + 256 * kc;
            int r = u >> 2, j = u & 3;
            cp_a[kc] = smbase + (uint32_t)(r * SSTR + j * 8) * 2;
            cp_b[kc] = cp_a[kc] + 128 * SSTR * 2;
            gm_a[kc] = Abase + (size_t)r * K + j * 8;
            gm_b[kc] = Bbase + (size_t)r * K + j * 8;
        }
    }

#define ISSUE_STAGE(st, kt)                                    \
    do {                                                       \
        uint32_t so_ = (uint32_t)(st) * STG_BYTES;             \
        cp16s(cp_a[0] + so_, gm_a[0] + (kt));                  \
        cp16s(cp_b[0] + so_, gm_b[0] + (kt));                  \
        cp16s(cp_a[1] + so_, gm_a[1] + (kt));                  \
        cp16s(cp_b[1] + so_, gm_b[1] + (kt));                  \
        asm volatile("cp.async.commit_group;" ::: "memory");   \
    } while (0)

    ISSUE_STAGE(0, 0);
    ISSUE_STAGE(1, BK);
    ISSUE_STAGE(2, 2 * BK);

    const int wid = tid >> 5;
    const int lane = tid & 31;
    const int wm = (wid & 1) * 64;      // warp row offset
    const int wn = (wid >> 1) * 32;     // warp col offset
    const int qr = lane >> 2;           // 0..7
    const int qc = lane & 3;            // 0..3
    // ldmatrix x4 lane mapping: m0 r0-7 k0, m1 r8-15 k0, m2 r0-7 k8, m3 r8-15 k8
    const int grp = lane >> 3;
    const int row_off = ((grp & 1) << 3) + (lane & 7);
    const int k_off = (grp >> 1) << 3;

    // ---- ldmatrix address precompute (loop-invariant bases)
    uint32_t ld_a[4], ld_b[2];
#pragma unroll
    for (int mt = 0; mt < 4; mt++)
        ld_a[mt] = smbase +
                   (uint32_t)((wm + mt * 16 + row_off) * SSTR + k_off) * 2;
#pragma unroll
    for (int nb = 0; nb < 2; nb++)
        ld_b[nb] = smbase +
                   (uint32_t)((128 + wn + nb * 16 + row_off) * SSTR + k_off) * 2;

    float acc[4][4][4];
#pragma unroll
    for (int i = 0; i < 4; i++)
#pragma unroll
        for (int j = 0; j < 4; j++)
#pragma unroll
            for (int k = 0; k < 4; k++) acc[i][j][k] = 0.f;

    const int nk = K / BK;
    for (int it = 0; it < nk; it++) {
        const int allow = nk - 1 - it;
        if (allow >= 2)      asm volatile("cp.async.wait_group 2;" ::: "memory");
        else if (allow == 1) asm volatile("cp.async.wait_group 1;" ::: "memory");
        else                 asm volatile("cp.async.wait_group 0;" ::: "memory");
        __syncthreads();

        if (it + 3 < nk) ISSUE_STAGE((it + 3) & (NSTG - 1), (it + 3) * BK);

        const uint32_t so = (uint32_t)(it & (NSTG - 1)) * STG_BYTES;

#pragma unroll
        for (int kk0 = 0; kk0 < BK; kk0 += 16) {
            uint32_t af[4][4], bf[4][2];
#pragma unroll
            for (int mt = 0; mt < 4; mt++)
                ldsm_x4a(af[mt][0], af[mt][1], af[mt][2], af[mt][3],
                         ld_a[mt] + so + kk0 * 2);
#pragma unroll
            for (int nb = 0; nb < 2; nb++) {
                uint32_t q0, q1, q2, q3;
                ldsm_x4a(q0, q1, q2, q3, ld_b[nb] + so + kk0 * 2);
                bf[2 * nb][0] = q0; bf[2 * nb + 1][0] = q1;
                bf[2 * nb][1] = q2; bf[2 * nb + 1][1] = q3;
            }
#pragma unroll
            for (int mt = 0; mt < 4; mt++)
#pragma unroll
                for (int nt = 0; nt < 4; nt++) {
                    float* c = acc[mt][nt];
                    asm volatile(
                        "mma.sync.aligned.m16n8k16.row.col.f32.f16.f16.f32 "
                        "{%0,%1,%2,%3}, {%4,%5,%6,%7}, {%8,%9}, {%0,%1,%2,%3};"
                        : "+f"(c[0]), "+f"(c[1]), "+f"(c[2]), "+f"(c[3])
                        : "r"(af[mt][0]), "r"(af[mt][1]), "r"(af[mt][2]), "r"(af[mt][3]),
                          "r"(bf[nt][0]), "r"(bf[nt][1]));
                }
        }
    }
#undef ISSUE_STAGE

    // Epilogue. Within a block the gate index (col>>10) is uniform.
    const int gate = bn >> 10;
#pragma unroll
    for (int mt = 0; mt < 4; mt++) {
#pragma unroll
        for (int nt = 0; nt < 4; nt++) {
            int r0 = bm + wm + mt * 16 + qr;
            int cc = bn + wn + nt * 8 + 2 * qc;
            float2 bb = *(const float2*)(&bias[cc]);
            float v0 = acc[mt][nt][0] + bb.x;
            float v1 = acc[mt][nt][1] + bb.y;
            float v2 = acc[mt][nt][2] + bb.x;
            float v3 = acc[mt][nt][3] + bb.y;
            size_t o0 = (size_t)r0 * N + cc;
            size_t o1 = (size_t)(r0 + 8) * N + cc;
            if (EPI == 0) {
                if (gate == 2) {          // z gate: tanh
                    v0 = tanhf(v0); v1 = tanhf(v1);
                    v2 = tanhf(v2); v3 = tanhf(v3);
                } else if (gate == 3) {   // o gate: sigmoid
                    v0 = __fdividef(1.f, 1.f + __expf(-v0));
                    v1 = __fdividef(1.f, 1.f + __expf(-v1));
                    v2 = __fdividef(1.f, 1.f + __expf(-v2));
                    v3 = __fdividef(1.f, 1.f + __expf(-v3));
                }
            } else {
                float2 r0v = *(const float2*)(&resid[o0]);
                float2 r1v = *(const float2*)(&resid[o1]);
                v0 += r0v.x; v1 += r0v.y;
                v2 += r1v.x; v3 += r1v.y;
            }
            *(float2*)(&Co[o0]) = make_float2(v0, v1);
            *(float2*)(&Co[o1]) = make_float2(v2, v3);
        }
    }
}

// ---------------------------------------------------------------------------
// Chunked parallel sLSTM scan (pair trick: 1 exp per step)
// ---------------------------------------------------------------------------
__global__ void __launch_bounds__(128) scan_a_kernel() {
    int ch = blockIdx.x * 128 + threadIdx.x;
    int ck = blockIdx.y;
    int b = ch >> 10, hd = ch & 1023;
    const float* Gp = g_gates + (size_t)b * T_ * NG + (size_t)ck * CHK * NG + hd;

    float F = 0.f, G = -3e38f, Pz = 0.f, Pn = 0.f;
#pragma unroll 4
    for (int j = 0; j < CHK; j++) {
        const float* p = Gp + (size_t)j * NG;
        float ig = p[0], fg = p[C_], zg = p[2 * C_];
        float u = fg + G - ig;
        float mn = ig + fmaxf(u, 0.f);
        float e = __expf(-fabsf(u));
        float ip = (u >= 0.f) ? e : 1.f;
        float fp = (u >= 0.f) ? 1.f : e;
        Pz = fp * Pz + ip * zg;
        Pn = fp * Pn + ip;
        G = mn;
        F += fg;
    }
    g_summ[ck * NCH + ch] = make_float4(F, G, Pz, Pn);
}

__global__ void __launch_bounds__(128) scan_b_kernel() {
    int ch = blockIdx.x * 128 + threadIdx.x;
    float c = 0.f, n = 1.f, m = 0.f;
#pragma unroll
    for (int j = 0; j < NC; j++) {
        g_inc[j * NCH + ch] = make_float4(c, n, m, 0.f);
        float4 s = g_summ[j * NCH + ch];
        float u = m + s.x - s.y;
        float mo = s.y + fmaxf(u, 0.f);
        float e = __expf(-fabsf(u));
        float a1 = (u >= 0.f) ? 1.f : e;
        float a2 = (u >= 0.f) ? e : 1.f;
        c = a1 * c + a2 * s.z;
        n = a1 * n + a2 * s.w;
        m = mo;
    }
}

__global__ void __launch_bounds__(128) scan_c_kernel() {
    int ch = blockIdx.x * 128 + threadIdx.x;
    int ck = blockIdx.y;
    int b = ch >> 10, hd = ch & 1023;
    const float* Gp = g_gates + (size_t)b * T_ * NG + (size_t)ck * CHK * NG + hd;
    float* hp = g_h + (size_t)b * T_ * C_ + (size_t)ck * CHK * C_ + hd;

    float4 st = g_inc[ck * NCH + ch];
    float c = st.x, n = st.y, m = st.z;
    float s1 = 0.f, s2 = 0.f;

#pragma unroll 4
    for (int j = 0; j < CHK; j++) {
        const float* p = Gp + (size_t)j * NG;
        float ig = p[0], fg = p[C_], zg = p[2 * C_], sg = p[3 * C_];
        float u = fg + m - ig;
        float mn = ig + fmaxf(u, 0.f);
        float e = __expf(-fabsf(u));
        float ip = (u >= 0.f) ? e : 1.f;
        float fp = (u >= 0.f) ? 1.f : e;
        c = fp * c + ip * zg;
        n = fp * n + ip;
        float h = __fdividef(sg * c, n + 1e-6f);
        hp[(size_t)j * C_] = h;
        s1 += h;
        s2 += h * h;
        m = mn;
    }
#pragma unroll
    for (int o = 16; o > 0; o >>= 1) {
        s1 += __shfl_down_sync(0xffffffffu, s1, o);
        s2 += __shfl_down_sync(0xffffffffu, s2, o);
    }
    if ((threadIdx.x & 31) == 0) {
        int grp = (b << 2) + (hd >> 8);
        atomicAdd(&g_sum[grp], s1);
        atomicAdd(&g_sqs[grp], s2);
    }
}

__global__ void prep_norm_kernel(const float* __restrict__ gn_w,
                                 const float* __restrict__ gn_b) {
    int idx = blockIdx.x * blockDim.x + threadIdx.x;
    int b = idx >> 10;
    int c = idx & (C_ - 1);
    int grp = (b << 2) + (c >> 8);
    const float inv_cnt = 1.f / (float)(T_ * D_);
    float mean = g_sum[grp] * inv_cnt;
    float var = g_sqs[grp] * inv_cnt - mean * mean;
    float rstd = rsqrtf(var + 1e-5f);
    float s = rstd * gn_w[c];
    g_ns[idx] = s;
    g_nt[idx] = gn_b[c] - mean * s;
}

__global__ void normalize_kernel() {
    int idx = blockIdx.x * blockDim.x + threadIdx.x;
    int c = idx & (C_ - 1);
    int b = idx >> 21;
    int bc = (b << 10) + c;
    g_hn[idx] = __float2half_rn(g_h[idx] * g_ns[bc] + g_nt[bc]);
}

// ---------------------------------------------------------------------------
// Launch
// ---------------------------------------------------------------------------
extern "C" void kernel_launch(void* const* d_in, const int* in_sizes, int n_in,
                              void* d_out, int out_size) {
    const float* x      = (const float*)d_in[0];
    const float* conv_w = (const float*)d_in[1];
    const float* conv_b = (const float*)d_in[2];
    const float* wx_w   = (const float*)d_in[3];
    const float* wx_b   = (const float*)d_in[4];
    const float* gn_w   = (const float*)d_in[5];
    const float* gn_b   = (const float*)d_in[6];
    const float* out_w  = (const float*)d_in[7];
    const float* out_b  = (const float*)d_in[8];
    float* out = (float*)d_out;

    (void)in_sizes; (void)n_in; (void)out_size;

    cudaFuncSetAttribute(gemm_fp16_kernel<0>,
                         cudaFuncAttributeMaxDynamicSharedMemorySize, DYN_BYTES);
    cudaFuncSetAttribute(gemm_fp16_kernel<1>,
                         cudaFuncAttributeMaxDynamicSharedMemorySize, DYN_BYTES);

    // 0) convert weights to fp16
    half_copy_kernel<0><<<(NG * C_ / 4 + 255) / 256, 256>>>(
        (const float4*)wx_w, NG * C_ / 4);
    half_copy_kernel<1><<<(C_ * C_ / 4 + 255) / 256, 256>>>(
        (const float4*)out_w, C_ * C_ / 4);

    // 1) conv + silu (fp16 output)
    conv_silu_kernel<<<(M_ * C_) / 256, 256>>>(x, conv_w, conv_b);

    // 2) gates GEMM (+bias, tanh on z, sigmoid on o)
    {
        dim3 g(NG / 128, M_ / 128);
        gemm_fp16_kernel<0><<<g, 256, DYN_BYTES>>>(wx_b, nullptr, nullptr,
                                                   M_, NG, C_);
    }

    // 3) parallel scan (+GroupNorm stats), norm coefficients, apply norm
    zero_stats_kernel<<<1, 32>>>();
    {
        dim3 g(NCH / 128, NC);
        scan_a_kernel<<<g, 128>>>();
        scan_b_kernel<<<NCH / 128, 128>>>();
        scan_c_kernel<<<g, 128>>>();
    }
    prep_norm_kernel<<<B_ * C_ / 256, 256>>>(gn_w, gn_b);
    normalize_kernel<<<(M_ * C_) / 256, 256>>>();

    // 4) output GEMM (+bias, +residual) -> d_out
    {
        dim3 g(C_ / 128, M_ / 128);
        gemm_fp16_kernel<1><<<g, 256, DYN_BYTES>>>(out_b, x, out, M_, C_, C_);
    }
}